// round 10
// baseline (speedup 1.0000x reference)
#include <cuda_runtime.h>
#include <math.h>
#include <cstdint>

#define B_   2
#define S_   2048
#define C_   1024
#define H_   16
#define DH_  64
#define M_   (B_ * S_)       // 4096 rows

// ---- scratch (device globals; no allocation allowed) ----
__device__ float g_Q[M_ * C_];           // tf32-rounded (GEMM epilogue)
__device__ float g_K[M_ * C_];           // tf32-rounded (GEMM epilogue)
__device__ float g_V[M_ * C_];           // exact fp32
__device__ float g_A[M_ * C_];           // attention output (tf32-rounded)
__device__ float g_X[M_ * C_];           // tf32-rounded x
__device__ float g_Wt[4 * C_ * C_];      // tf32-rounded weights
__device__ float g_m1[B_ * H_ * S_];     // full-row max of scores (already /8)
__device__ float g_vs[B_ * H_ * DH_];    // sum over all keys of V per (b,h)

__device__ __forceinline__ unsigned f2tf(float x) {
    unsigned r;
    asm("cvt.rna.tf32.f32 %0, %1;" : "=r"(r) : "f"(x));
    return r;
}

__device__ __forceinline__ uint32_t s2u(const void* p) {
    uint32_t a;
    asm("{ .reg .u64 t; cvta.to.shared.u64 t, %1; cvt.u32.u64 %0, t; }"
        : "=r"(a) : "l"(p));
    return a;
}

__device__ __forceinline__ void cp16(uint32_t d, const void* s) {
    asm volatile("cp.async.cg.shared.global [%0], [%1], 16;" :: "r"(d), "l"(s));
}
#define CP_COMMIT() asm volatile("cp.async.commit_group;" ::: "memory")
#define CP_WAIT0()  asm volatile("cp.async.wait_group 0;" ::: "memory")
#define CP_WAIT2()  asm volatile("cp.async.wait_group 2;" ::: "memory")

#define MMA_TF32(c, a, b)                                                     \
    asm volatile(                                                             \
        "mma.sync.aligned.m16n8k8.row.col.f32.tf32.tf32.f32 "                 \
        "{%0,%1,%2,%3},{%4,%5,%6,%7},{%8,%9},{%0,%1,%2,%3};"                  \
        : "+f"((c)[0]), "+f"((c)[1]), "+f"((c)[2]), "+f"((c)[3])              \
        : "r"((a)[0]), "r"((a)[1]), "r"((a)[2]), "r"((a)[3]),                 \
          "r"((b)[0]), "r"((b)[1]))

// ============================================================================
// tf32 rounding kernel
// ============================================================================
__global__ __launch_bounds__(256) void round_tf32(
    const float* __restrict__ src, float* __restrict__ dst)
{
    const int i = blockIdx.x * 256 + threadIdx.x;
    float4 v = ((const float4*)src)[i];
    uint4 t;
    t.x = f2tf(v.x); t.y = f2tf(v.y); t.z = f2tf(v.z); t.w = f2tf(v.w);
    ((uint4*)dst)[i] = t;
}

// ============================================================================
// cp.async 3-stage tf32 GEMM (R9 winner) + optional tf32-rounded epilogue
// ============================================================================
#define AS_WORDS (128 * 36)
#define BS_WORDS (32 * 128)
#define GEMM_SMEM_BYTES (3 * (AS_WORDS + BS_WORDS) * 4)

__device__ __forceinline__ void issue_tile(
    const float* __restrict__ A, const float* __restrict__ B,
    int K, int N, int bm, int bn, int kb,
    uint32_t sbase, int stage, int tid)
{
#pragma unroll
    for (int u = 0; u < 4; ++u) {
        const int f = tid + 256 * u;
        const int row = f >> 3;
        const int k4 = (f & 7) * 4;
        cp16(sbase + (uint32_t)(stage * AS_WORDS + row * 36 + k4) * 4,
             A + (size_t)(bm + row) * K + kb + k4);
    }
    const int bk = tid >> 3;
    const int n0 = (tid & 7) * 16;
    const unsigned sw = (bk & 3) << 3;
#pragma unroll
    for (int j = 0; j < 4; ++j) {
        cp16(sbase + (uint32_t)(3 * AS_WORDS + stage * BS_WORDS + bk * 128 +
                                ((n0 + j * 4) ^ sw)) * 4,
             B + (size_t)(kb + bk) * N + bn + n0 + j * 4);
    }
}

__device__ __forceinline__ void gemm_ca_body(
    const float* __restrict__ A, const float* __restrict__ B,
    float* __restrict__ C, int N, int K, bool round_out)
{
    extern __shared__ unsigned smbuf[];
    const uint32_t sbase = s2u(smbuf);

    const int tid = threadIdx.x;
    const int bm = blockIdx.y * 128;
    const int bn = blockIdx.x * 128;

    const int wid  = tid >> 5;
    const int lane = tid & 31;
    const int g    = lane >> 2;
    const int tig  = lane & 3;
    const int warpM = wid >> 1;
    const int warpN = wid & 1;
    const unsigned swz = tig << 3;

    float c[2][8][4];
#pragma unroll
    for (int i = 0; i < 2; ++i)
#pragma unroll
        for (int j = 0; j < 8; ++j)
#pragma unroll
            for (int r = 0; r < 4; ++r) c[i][j][r] = 0.f;

    const int nt = K >> 5;

    issue_tile(A, B, K, N, bm, bn, 0,  sbase, 0, tid); CP_COMMIT();
    issue_tile(A, B, K, N, bm, bn, 32, sbase, 1, tid); CP_COMMIT();

    for (int t = 0; t < nt; ++t) {
        if (t + 2 < nt)
            issue_tile(A, B, K, N, bm, bn, (t + 2) * 32, sbase, (t + 2) % 3, tid);
        CP_COMMIT();
        CP_WAIT2();
        __syncthreads();

        const unsigned* Ab = smbuf + (t % 3) * AS_WORDS;
        const unsigned* Bb = smbuf + 3 * AS_WORDS + (t % 3) * BS_WORDS;

#pragma unroll
        for (int ks = 0; ks < 4; ++ks) {
            const int k0 = ks * 8;
            unsigned a[2][4];
#pragma unroll
            for (int m2 = 0; m2 < 2; ++m2) {
                const int mr = warpM * 32 + m2 * 16;
                a[m2][0] = Ab[(mr + g) * 36 + k0 + tig];
                a[m2][1] = Ab[(mr + g + 8) * 36 + k0 + tig];
                a[m2][2] = Ab[(mr + g) * 36 + k0 + tig + 4];
                a[m2][3] = Ab[(mr + g + 8) * 36 + k0 + tig + 4];
            }
#pragma unroll
            for (int j = 0; j < 8; ++j) {
                unsigned b[2];
                const unsigned nc = (unsigned)(warpN * 64 + j * 8 + g) ^ swz;
                b[0] = Bb[(k0 + tig) * 128 + nc];
                b[1] = Bb[(k0 + tig + 4) * 128 + nc];
                MMA_TF32(c[0][j], a[0], b);
                MMA_TF32(c[1][j], a[1], b);
            }
        }
        __syncthreads();
    }

#pragma unroll
    for (int m2 = 0; m2 < 2; ++m2) {
#pragma unroll
        for (int j = 0; j < 8; ++j) {
            const int row = bm + warpM * 32 + m2 * 16 + g;
            const int col = bn + warpN * 64 + j * 8 + 2 * tig;
            float2 v0 = make_float2(c[m2][j][0], c[m2][j][1]);
            float2 v1 = make_float2(c[m2][j][2], c[m2][j][3]);
            if (round_out) {
                v0.x = __uint_as_float(f2tf(v0.x));
                v0.y = __uint_as_float(f2tf(v0.y));
                v1.x = __uint_as_float(f2tf(v1.x));
                v1.y = __uint_as_float(f2tf(v1.y));
            }
            *(float2*)&C[(size_t)row * N + col]       = v0;
            *(float2*)&C[(size_t)(row + 8) * N + col] = v1;
        }
    }
}

__global__ __launch_bounds__(256, 2) void tgemm_ca(
    const float* __restrict__ A, const float* __restrict__ B,
    float* __restrict__ C, int N, int K)
{
    gemm_ca_body(A, B, C, N, K, false);
}

__global__ __launch_bounds__(256, 2) void tgemm_ca_qkv(
    const float* __restrict__ A, const float* __restrict__ W,
    float* __restrict__ C0, float* __restrict__ C1, float* __restrict__ C2)
{
    const int z = blockIdx.z;
    float* C = (z == 0) ? C0 : (z == 1) ? C1 : C2;
    gemm_ca_body(A, W + (size_t)z * C_ * C_, C, C_, C_, z < 2);  // round Q,K
}

// ============================================================================
// tf32 score row-max: Q,K pre-rounded; K tiles via double-buffered cp.async.
// ============================================================================
__global__ __launch_bounds__(256, 2) void score_max_t(
    const float* __restrict__ Q, const float* __restrict__ K,
    float* __restrict__ m1)
{
    __shared__ __align__(16) unsigned Ks[2][64][68];
    __shared__ float buf[4][64];

    const int bh = blockIdx.y;
    const int b = bh >> 4, h = bh & 15;
    const int q0 = blockIdx.x * 64;
    const int tid = threadIdx.x;
    const int rowbase = (b * S_) * C_ + h * DH_;
    const uint32_t ksb = s2u(Ks);

    const int wid  = tid >> 5;
    const int lane = tid & 31;
    const int g    = lane >> 2;
    const int tig  = lane & 3;
    const int warpM = wid & 3;
    const int warpN = wid >> 2;

    // stage Q tile into Ks[0] (pre-rounded; plain copy), extract fragments
    {
        const int r  = tid >> 2;
        const int c0 = (tid & 3) * 16;
        const float* qp = Q + rowbase + (q0 + r) * C_ + c0;
#pragma unroll
        for (int j = 0; j < 4; ++j)
            *(uint4*)&Ks[0][r][c0 + j * 4] = *(const uint4*)(qp + j * 4);
    }
    __syncthreads();

    unsigned bq[4][8][2];
#pragma unroll
    for (int na = 0; na < 4; ++na) {
        const int nc = warpN * 32 + na * 8 + g;
#pragma unroll
        for (int ks = 0; ks < 8; ++ks) {
            bq[na][ks][0] = Ks[0][nc][ks * 8 + tig];
            bq[na][ks][1] = Ks[0][nc][ks * 8 + tig + 4];
        }
    }
    __syncthreads();

    float rmax[4][2];
#pragma unroll
    for (int na = 0; na < 4; ++na) { rmax[na][0] = -1e30f; rmax[na][1] = -1e30f; }

    const int ld_r = tid >> 2;           // 0..63
    const int ld_c = (tid & 3) * 16;     // 0,16,32,48

    // prologue: tile 0 -> buffer 0
#pragma unroll
    for (int j = 0; j < 4; ++j)
        cp16(ksb + (uint32_t)(ld_r * 68 + ld_c + j * 4) * 4,
             K + rowbase + ld_r * C_ + ld_c + j * 4);
    CP_COMMIT();

    const int nt = S_ / 64;
    for (int t = 0; t < nt; ++t) {
        const int cur = t & 1;
        CP_WAIT0();
        __syncthreads();

        if (t + 1 < nt) {
            const int nb = (t + 1) & 1;
            const float* kp = K + rowbase + ((t + 1) * 64 + ld_r) * C_ + ld_c;
#pragma unroll
            for (int j = 0; j < 4; ++j)
                cp16(ksb + (uint32_t)(nb * 64 * 68 + ld_r * 68 + ld_c + j * 4) * 4,
                     kp + j * 4);
            CP_COMMIT();
        }

        float c[4][4];
#pragma unroll
        for (int na = 0; na < 4; ++na)
#pragma unroll
            for (int r = 0; r < 4; ++r) c[na][r] = 0.f;

        const int mr = warpM * 16;
#pragma unroll
        for (int ks = 0; ks < 8; ++ks) {
            const int k0 = ks * 8;
            unsigned a[4];
            a[0] = Ks[cur][mr + g][k0 + tig];
            a[1] = Ks[cur][mr + g + 8][k0 + tig];
            a[2] = Ks[cur][mr + g][k0 + tig + 4];
            a[3] = Ks[cur][mr + g + 8][k0 + tig + 4];
#pragma unroll
            for (int na = 0; na < 4; ++na)
                MMA_TF32(c[na], a, bq[na][ks]);
        }

#pragma unroll
        for (int na = 0; na < 4; ++na) {
            rmax[na][0] = fmaxf(rmax[na][0], fmaxf(c[na][0], c[na][2]));
            rmax[na][1] = fmaxf(rmax[na][1], fmaxf(c[na][1], c[na][3]));
        }
    }

#pragma unroll
    for (int off = 4; off <= 16; off <<= 1)
#pragma unroll
        for (int na = 0; na < 4; ++na) {
            rmax[na][0] = fmaxf(rmax[na][0], __shfl_xor_sync(0xffffffffu, rmax[na][0], off));
            rmax[na][1] = fmaxf(rmax[na][1], __shfl_xor_sync(0xffffffffu, rmax[na][1], off));
        }

    if (g == 0) {
#pragma unroll
        for (int na = 0; na < 4; ++na) {
            buf[warpM][warpN * 32 + na * 8 + tig * 2 + 0] = rmax[na][0];
            buf[warpM][warpN * 32 + na * 8 + tig * 2 + 1] = rmax[na][1];
        }
    }
    __syncthreads();
    if (tid < 64) {
        float m = fmaxf(fmaxf(buf[0][tid], buf[1][tid]),
                        fmaxf(buf[2][tid], buf[3][tid]));
        m1[bh * S_ + q0 + tid] = m * 0.125f;
    }
}

// ============================================================================
// V column sums per (b,h) — V exact fp32
// ============================================================================
__global__ __launch_bounds__(256) void vsum_k(
    const float* __restrict__ V, float* __restrict__ vs)
{
    __shared__ float red[4][64];
    const int bh = blockIdx.x;
    const int b = bh >> 4, h = bh & 15;
    const int tid = threadIdx.x;
    const int d = tid & 63, g = tid >> 6;
    const float* p = V + (b * S_) * C_ + h * DH_ + d;
    float s = 0.f;
    for (int k = g; k < S_; k += 4) s += p[k * C_];
    red[g][d] = s;
    __syncthreads();
    if (tid < 64)
        vs[bh * 64 + tid] = red[0][tid] + red[1][tid] + red[2][tid] + red[3][tid];
}

// ============================================================================
// Tensor-core banded attention. Q,K pre-rounded; K,V tiles via
// double-buffered cp.async (dynamic smem). V consumed as raw fp32 bits
// (HW tf32 truncation). Output tf32-rounded.
// smem words: Qs 64*68=4352 | Ks 2*32*76=4864 | Vs 4864 | Ws 32*76=2432 |
//             zred 128  -> total 16640 words = 66560 B
// ============================================================================
#define BAND_QS    0
#define BAND_KS    4352
#define BAND_VS    9216
#define BAND_WS    14080
#define BAND_ZR    16512
#define BAND_SMEM_BYTES (16640 * 4)

__global__ __launch_bounds__(256) void band_attn_t(
    const float* __restrict__ Q, const float* __restrict__ K,
    const float* __restrict__ V, const float* __restrict__ m1,
    const float* __restrict__ vs, float* __restrict__ O)
{
    extern __shared__ unsigned bsm[];
    unsigned* Qs = bsm + BAND_QS;
    unsigned* Ws = bsm + BAND_WS;
    float* zred  = (float*)(bsm + BAND_ZR);
    const uint32_t sb = s2u(bsm);

    const int bh = blockIdx.y;
    const int b = bh >> 4, h = bh & 15;
    const int q0 = blockIdx.x * 64;
    const int tid = threadIdx.x;
    const int rowbase = (b * S_) * C_ + h * DH_;

    const int wid  = tid >> 5;
    const int lane = tid & 31;
    const int g    = lane >> 2;
    const int tig  = lane & 3;
    const int wm1 = wid & 1;
    const int wn1 = wid >> 1;
    const int wm2 = wid >> 1;
    const int wn2 = wid & 1;

    // load Q tile (pre-rounded, plain copy)
    {
        const int r  = tid >> 2;
        const int c0 = (tid & 3) * 16;
        const float* qp = Q + rowbase + (q0 + r) * C_ + c0;
#pragma unroll
        for (int j = 0; j < 4; ++j)
            *(uint4*)&Qs[r * 68 + c0 + j * 4] = *(const uint4*)(qp + j * 4);
    }
    __syncthreads();

    unsigned bq[2][8][2];
#pragma unroll
    for (int na = 0; na < 2; ++na) {
        const int nc = wn1 * 16 + na * 8 + g;
#pragma unroll
        for (int ks = 0; ks < 8; ++ks) {
            bq[na][ks][0] = Qs[nc * 68 + ks * 8 + tig];
            bq[na][ks][1] = Qs[nc * 68 + ks * 8 + tig + 4];
        }
    }
    float m1c[2][2];
#pragma unroll
    for (int na = 0; na < 2; ++na) {
        const int qc = q0 + wn1 * 16 + na * 8 + 2 * tig;
        m1c[na][0] = m1[bh * S_ + qc];
        m1c[na][1] = m1[bh * S_ + qc + 1];
    }

    float o[4][4];
#pragma unroll
    for (int na = 0; na < 4; ++na)
#pragma unroll
        for (int r = 0; r < 4; ++r) o[na][r] = 0.f;
    float zp[2][2] = {{0.f, 0.f}, {0.f, 0.f}};

    const int klo  = (q0 >= 128) ? q0 - 128 : 0;
    const int kend = (q0 + 192 < S_) ? q0 + 192 : S_;
    const int nt = (kend - klo) >> 5;

    // cp.async issue helper (inlined twice): 2 chunks K + 2 chunks V per thread
    const int ld_r = tid >> 3;            // via f = tid + 256u → handled below

    // prologue: tile 0
    {
#pragma unroll
        for (int u = 0; u < 2; ++u) {
            const int f = tid + 256 * u;      // 0..511
            const int row = f >> 4;           // 0..31
            const int c4 = (f & 15) * 4;
            const float* kp = K + rowbase + (klo + row) * C_ + c4;
            const float* vp = V + rowbase + (klo + row) * C_ + c4;
            cp16(sb + (uint32_t)(BAND_KS + row * 76 + c4) * 4, kp);
            cp16(sb + (uint32_t)(BAND_VS + row * 76 + c4) * 4, vp);
        }
        CP_COMMIT();
    }
    (void)ld_r;

    for (int t = 0; t < nt; ++t) {
        const int cur = t & 1;
        CP_WAIT0();
        __syncthreads();   // tile t resident; all warps done GEMM2(t-1)

        if (t + 1 < nt) {
            const int nb = (t + 1) & 1;
            const int kt1 = klo + (t + 1) * 32;
#pragma unroll
            for (int u = 0; u < 2; ++u) {
                const int f = tid + 256 * u;
                const int row = f >> 4;
                const int c4 = (f & 15) * 4;
                cp16(sb + (uint32_t)(BAND_KS + nb * 2432 + row * 76 + c4) * 4,
                     K + rowbase + (kt1 + row) * C_ + c4);
                cp16(sb + (uint32_t)(BAND_VS + nb * 2432 + row * 76 + c4) * 4,
                     V + rowbase + (kt1 + row) * C_ + c4);
            }
            CP_COMMIT();
        }

        const unsigned* Kc = bsm + BAND_KS + cur * 2432;
        const unsigned* Vc = bsm + BAND_VS + cur * 2432;
        const int kt = klo + t * 32;

        // ---- GEMM1: S^T[key][q] ----
        float s[2][4];
#pragma unroll
        for (int na = 0; na < 2; ++na)
#pragma unroll
            for (int r = 0; r < 4; ++r) s[na][r] = 0.f;

        const int mr1 = wm1 * 16;
#pragma unroll
        for (int ks = 0; ks < 8; ++ks) {
            const int k0 = ks * 8;
            unsigned a[4];
            a[0] = Kc[(mr1 + g) * 76 + k0 + tig];
            a[1] = Kc[(mr1 + g + 8) * 76 + k0 + tig];
            a[2] = Kc[(mr1 + g) * 76 + k0 + tig + 4];
            a[3] = Kc[(mr1 + g + 8) * 76 + k0 + tig + 4];
            MMA_TF32(s[0], a, bq[0][ks]);
            MMA_TF32(s[1], a, bq[1][ks]);
        }

        // ---- exp / band mask / Z -> W^T ----
#pragma unroll
        for (int na = 0; na < 2; ++na) {
            const int colq = wn1 * 16 + na * 8 + 2 * tig;
#pragma unroll
            for (int r2 = 0; r2 < 2; ++r2) {
                const int keyrow = wm1 * 16 + g + r2 * 8;
                const int key = kt + keyrow;
#pragma unroll
                for (int j = 0; j < 2; ++j) {
                    const float sv = s[na][r2 * 2 + j];
                    const int d = key - (q0 + colq + j);
                    float tt = __expf(sv * 0.125f - m1c[na][j]);
                    float w = __expf(tt) - 1.0f;
                    if (d < -128 || d > 127) w = 0.f;
                    const unsigned wt = f2tf(w);
                    zp[na][j] += __uint_as_float(wt);
                    Ws[keyrow * 76 + colq + j] = wt;
                }
            }
        }
        __syncthreads();   // W^T visible

        // ---- GEMM2: O += W @ V ----
        const int mr2 = wm2 * 16;
#pragma unroll
        for (int ks = 0; ks < 4; ++ks) {
            const int k0 = ks * 8;
            unsigned a[4];
            a[0] = Ws[(k0 + tig) * 76 + mr2 + g];
            a[1] = Ws[(k0 + tig) * 76 + mr2 + g + 8];
            a[2] = Ws[(k0 + tig + 4) * 76 + mr2 + g];
            a[3] = Ws[(k0 + tig + 4) * 76 + mr2 + g + 8];
#pragma unroll
            for (int na = 0; na < 4; ++na) {
                unsigned bb[2];
                const int nc = wn2 * 32 + na * 8 + g;
                bb[0] = Vc[(k0 + tig) * 76 + nc];
                bb[1] = Vc[(k0 + tig + 4) * 76 + nc];
                MMA_TF32(o[na], a, bb);
            }
        }
    }

    // ---- Z reduction ----
#pragma unroll
    for (int off = 4; off <= 16; off <<= 1)
#pragma unroll
        for (int na = 0; na < 2; ++na) {
            zp[na][0] += __shfl_xor_sync(0xffffffffu, zp[na][0], off);
            zp[na][1] += __shfl_xor_sync(0xffffffffu, zp[na][1], off);
        }
    if (g == 0) {
#pragma unroll
        for (int na = 0; na < 2; ++na) {
            zred[wm1 * 64 + wn1 * 16 + na * 8 + 2 * tig + 0] = zp[na][0];
            zred[wm1 * 64 + wn1 * 16 + na * 8 + 2 * tig + 1] = zp[na][1];
        }
    }
    __syncthreads();

    // ---- epilogue ----
    const float* vsp = vs + bh * 64;
#pragma unroll
    for (int r2 = 0; r2 < 2; ++r2) {
        const int row = wm2 * 16 + g + r2 * 8;
        const float inv = 1.0f / ((float)S_ + zred[row] + zred[64 + row]);
        float* op = O + rowbase + (q0 + row) * C_;
#pragma unroll
        for (int na = 0; na < 4; ++na) {
            const int col = wn2 * 32 + na * 8 + 2 * tig;
            float2 ov;
            ov.x = __uint_as_float(f2tf((o[na][r2 * 2 + 0] + vsp[col])     * inv));
            ov.y = __uint_as_float(f2tf((o[na][r2 * 2 + 1] + vsp[col + 1]) * inv));
            *(float2*)(op + col) = ov;
        }
    }
}

// ============================================================================
extern "C" void kernel_launch(void* const* d_in, const int* in_sizes, int n_in,
                              void* d_out, int out_size)
{
    (void)in_sizes; (void)n_in; (void)out_size;
    const float* x  = (const float*)d_in[0];
    const float* Wq = (const float*)d_in[1];
    const float* Wk = (const float*)d_in[2];
    const float* Wv = (const float*)d_in[3];
    const float* Wo = (const float*)d_in[4];
    float* out = (float*)d_out;

    float *Qp, *Kp, *Vp, *Ap, *Xp, *Wtp, *m1p, *vsp;
    cudaGetSymbolAddress((void**)&Qp,  g_Q);
    cudaGetSymbolAddress((void**)&Kp,  g_K);
    cudaGetSymbolAddress((void**)&Vp,  g_V);
    cudaGetSymbolAddress((void**)&Ap,  g_A);
    cudaGetSymbolAddress((void**)&Xp,  g_X);
    cudaGetSymbolAddress((void**)&Wtp, g_Wt);
    cudaGetSymbolAddress((void**)&m1p, g_m1);
    cudaGetSymbolAddress((void**)&vsp, g_vs);

    cudaFuncSetAttribute(tgemm_ca,
                         cudaFuncAttributeMaxDynamicSharedMemorySize,
                         GEMM_SMEM_BYTES);
    cudaFuncSetAttribute(tgemm_ca_qkv,
                         cudaFuncAttributeMaxDynamicSharedMemorySize,
                         GEMM_SMEM_BYTES);
    cudaFuncSetAttribute(band_attn_t,
                         cudaFuncAttributeMaxDynamicSharedMemorySize,
                         BAND_SMEM_BYTES);

    round_tf32<<<(M_ * C_) / 1024, 256>>>(x, Xp);
    round_tf32<<<(C_ * C_) / 1024, 256>>>(Wq, Wtp + 0 * C_ * C_);
    round_tf32<<<(C_ * C_) / 1024, 256>>>(Wk, Wtp + 1 * C_ * C_);
    round_tf32<<<(C_ * C_) / 1024, 256>>>(Wv, Wtp + 2 * C_ * C_);
    round_tf32<<<(C_ * C_) / 1024, 256>>>(Wo, Wtp + 3 * C_ * C_);

    dim3 gq(C_ / 128, M_ / 128, 3);         // (8, 32, 3)
    tgemm_ca_qkv<<<gq, 256, GEMM_SMEM_BYTES>>>(Xp, Wtp, Qp, Kp, Vp);

    score_max_t<<<dim3(S_ / 64, B_ * H_), 256>>>(Qp, Kp, m1p);
    vsum_k<<<B_ * H_, 256>>>(Vp, vsp);
    band_attn_t<<<dim3(S_ / 64, B_ * H_), 256, BAND_SMEM_BYTES>>>(
        Qp, Kp, Vp, m1p, vsp, Ap);

    dim3 gg(C_ / 128, M_ / 128);            // (8, 32)
    tgemm_ca<<<gg, 256, GEMM_SMEM_BYTES>>>(Ap, Wtp + 3 * C_ * C_, out, C_, C_);
}

// round 11
// speedup vs baseline: 1.0339x; 1.0339x over previous
#include <cuda_runtime.h>
#include <math.h>
#include <cstdint>

#define B_   2
#define S_   2048
#define C_   1024
#define H_   16
#define DH_  64
#define M_   (B_ * S_)       // 4096 rows

// ---- scratch (device globals; no allocation allowed) ----
__device__ float g_Q[M_ * C_];           // tf32-rounded (GEMM epilogue)
__device__ float g_K[M_ * C_];           // tf32-rounded (GEMM epilogue)
__device__ float g_V[M_ * C_];           // exact fp32
__device__ float g_A[M_ * C_];           // attention output (tf32-rounded)
__device__ float g_X[M_ * C_];           // tf32-rounded x
__device__ float g_Wt[4 * C_ * C_];      // tf32-rounded weights
__device__ float g_m1[B_ * H_ * S_];     // full-row max of scores (already /8)
__device__ float g_vs[B_ * H_ * DH_];    // sum over all keys of V per (b,h)

__device__ __forceinline__ unsigned f2tf(float x) {
    unsigned r;
    asm("cvt.rna.tf32.f32 %0, %1;" : "=r"(r) : "f"(x));
    return r;
}

__device__ __forceinline__ uint32_t s2u(const void* p) {
    uint32_t a;
    asm("{ .reg .u64 t; cvta.to.shared.u64 t, %1; cvt.u32.u64 %0, t; }"
        : "=r"(a) : "l"(p));
    return a;
}

__device__ __forceinline__ void cp16(uint32_t d, const void* s) {
    asm volatile("cp.async.cg.shared.global [%0], [%1], 16;" :: "r"(d), "l"(s));
}
#define CP_COMMIT() asm volatile("cp.async.commit_group;" ::: "memory")
#define CP_WAIT2()  asm volatile("cp.async.wait_group 2;" ::: "memory")

#define MMA_TF32(c, a, b)                                                     \
    asm volatile(                                                             \
        "mma.sync.aligned.m16n8k8.row.col.f32.tf32.tf32.f32 "                 \
        "{%0,%1,%2,%3},{%4,%5,%6,%7},{%8,%9},{%0,%1,%2,%3};"                  \
        : "+f"((c)[0]), "+f"((c)[1]), "+f"((c)[2]), "+f"((c)[3])              \
        : "r"((a)[0]), "r"((a)[1]), "r"((a)[2]), "r"((a)[3]),                 \
          "r"((b)[0]), "r"((b)[1]))

// ============================================================================
// Fused tf32 rounding: x (1M float4) then Wq,Wk,Wv,Wo (256K float4 each).
// ============================================================================
__global__ __launch_bounds__(256) void round_all(
    const float* __restrict__ x,
    const float* __restrict__ W0, const float* __restrict__ W1,
    const float* __restrict__ W2, const float* __restrict__ W3,
    float* __restrict__ X, float* __restrict__ Wt)
{
    const int i = blockIdx.x * 256 + threadIdx.x;   // 0 .. 2M-1 float4
    const float* src;
    float* dst;
    if (i < (M_ * C_ / 4)) {
        src = x;  dst = X;
        const int j = i;
        float4 v = ((const float4*)src)[j];
        uint4 t;
        t.x = f2tf(v.x); t.y = f2tf(v.y); t.z = f2tf(v.z); t.w = f2tf(v.w);
        ((uint4*)dst)[j] = t;
    } else {
        const int w = i - (M_ * C_ / 4);            // 0 .. 1M-1
        const int z = w >> 18;                      // 256K float4 per weight
        const int j = w & ((1 << 18) - 1);
        src = (z == 0) ? W0 : (z == 1) ? W1 : (z == 2) ? W2 : W3;
        dst = Wt + (size_t)z * C_ * C_;
        float4 v = ((const float4*)src)[j];
        uint4 t;
        t.x = f2tf(v.x); t.y = f2tf(v.y); t.z = f2tf(v.z); t.w = f2tf(v.w);
        ((uint4*)dst)[j] = t;
    }
}

// ============================================================================
// cp.async 3-stage tf32 GEMM (R9 winner) + optional tf32-rounded epilogue
// ============================================================================
#define AS_WORDS (128 * 36)
#define BS_WORDS (32 * 128)
#define GEMM_SMEM_BYTES (3 * (AS_WORDS + BS_WORDS) * 4)

__device__ __forceinline__ void issue_tile(
    const float* __restrict__ A, const float* __restrict__ B,
    int K, int N, int bm, int bn, int kb,
    uint32_t sbase, int stage, int tid)
{
#pragma unroll
    for (int u = 0; u < 4; ++u) {
        const int f = tid + 256 * u;
        const int row = f >> 3;
        const int k4 = (f & 7) * 4;
        cp16(sbase + (uint32_t)(stage * AS_WORDS + row * 36 + k4) * 4,
             A + (size_t)(bm + row) * K + kb + k4);
    }
    const int bk = tid >> 3;
    const int n0 = (tid & 7) * 16;
    const unsigned sw = (bk & 3) << 3;
#pragma unroll
    for (int j = 0; j < 4; ++j) {
        cp16(sbase + (uint32_t)(3 * AS_WORDS + stage * BS_WORDS + bk * 128 +
                                ((n0 + j * 4) ^ sw)) * 4,
             B + (size_t)(kb + bk) * N + bn + n0 + j * 4);
    }
}

__device__ __forceinline__ void gemm_ca_body(
    const float* __restrict__ A, const float* __restrict__ B,
    float* __restrict__ C, int N, int K, bool round_out)
{
    extern __shared__ unsigned smbuf[];
    const uint32_t sbase = s2u(smbuf);

    const int tid = threadIdx.x;
    const int bm = blockIdx.y * 128;
    const int bn = blockIdx.x * 128;

    const int wid  = tid >> 5;
    const int lane = tid & 31;
    const int g    = lane >> 2;
    const int tig  = lane & 3;
    const int warpM = wid >> 1;
    const int warpN = wid & 1;
    const unsigned swz = tig << 3;

    float c[2][8][4];
#pragma unroll
    for (int i = 0; i < 2; ++i)
#pragma unroll
        for (int j = 0; j < 8; ++j)
#pragma unroll
            for (int r = 0; r < 4; ++r) c[i][j][r] = 0.f;

    const int nt = K >> 5;

    issue_tile(A, B, K, N, bm, bn, 0,  sbase, 0, tid); CP_COMMIT();
    issue_tile(A, B, K, N, bm, bn, 32, sbase, 1, tid); CP_COMMIT();

    for (int t = 0; t < nt; ++t) {
        if (t + 2 < nt)
            issue_tile(A, B, K, N, bm, bn, (t + 2) * 32, sbase, (t + 2) % 3, tid);
        CP_COMMIT();
        CP_WAIT2();
        __syncthreads();

        const unsigned* Ab = smbuf + (t % 3) * AS_WORDS;
        const unsigned* Bb = smbuf + 3 * AS_WORDS + (t % 3) * BS_WORDS;

#pragma unroll
        for (int ks = 0; ks < 4; ++ks) {
            const int k0 = ks * 8;
            unsigned a[2][4];
#pragma unroll
            for (int m2 = 0; m2 < 2; ++m2) {
                const int mr = warpM * 32 + m2 * 16;
                a[m2][0] = Ab[(mr + g) * 36 + k0 + tig];
                a[m2][1] = Ab[(mr + g + 8) * 36 + k0 + tig];
                a[m2][2] = Ab[(mr + g) * 36 + k0 + tig + 4];
                a[m2][3] = Ab[(mr + g + 8) * 36 + k0 + tig + 4];
            }
#pragma unroll
            for (int j = 0; j < 8; ++j) {
                unsigned b[2];
                const unsigned nc = (unsigned)(warpN * 64 + j * 8 + g) ^ swz;
                b[0] = Bb[(k0 + tig) * 128 + nc];
                b[1] = Bb[(k0 + tig + 4) * 128 + nc];
                MMA_TF32(c[0][j], a[0], b);
                MMA_TF32(c[1][j], a[1], b);
            }
        }
        __syncthreads();
    }

#pragma unroll
    for (int m2 = 0; m2 < 2; ++m2) {
#pragma unroll
        for (int j = 0; j < 8; ++j) {
            const int row = bm + warpM * 32 + m2 * 16 + g;
            const int col = bn + warpN * 64 + j * 8 + 2 * tig;
            float2 v0 = make_float2(c[m2][j][0], c[m2][j][1]);
            float2 v1 = make_float2(c[m2][j][2], c[m2][j][3]);
            if (round_out) {
                v0.x = __uint_as_float(f2tf(v0.x));
                v0.y = __uint_as_float(f2tf(v0.y));
                v1.x = __uint_as_float(f2tf(v1.x));
                v1.y = __uint_as_float(f2tf(v1.y));
            }
            *(float2*)&C[(size_t)row * N + col]       = v0;
            *(float2*)&C[(size_t)(row + 8) * N + col] = v1;
        }
    }
}

__global__ __launch_bounds__(256, 2) void tgemm_ca(
    const float* __restrict__ A, const float* __restrict__ B,
    float* __restrict__ C, int N, int K)
{
    gemm_ca_body(A, B, C, N, K, false);
}

__global__ __launch_bounds__(256, 2) void tgemm_ca_qkv(
    const float* __restrict__ A, const float* __restrict__ W,
    float* __restrict__ C0, float* __restrict__ C1, float* __restrict__ C2)
{
    const int z = blockIdx.z;
    float* C = (z == 0) ? C0 : (z == 1) ? C1 : C2;
    gemm_ca_body(A, W + (size_t)z * C_ * C_, C, C_, C_, z < 2);  // round Q,K
}

// ============================================================================
// tf32 score row-max (R9-winning structure; Q,K pre-rounded -> plain copies)
// ============================================================================
__global__ __launch_bounds__(256, 2) void score_max_t(
    const float* __restrict__ Q, const float* __restrict__ K,
    float* __restrict__ m1)
{
    __shared__ unsigned Ks[2][64][68];
    __shared__ float buf[4][64];

    const int bh = blockIdx.y;
    const int b = bh >> 4, h = bh & 15;
    const int q0 = blockIdx.x * 64;
    const int tid = threadIdx.x;
    const int rowbase = (b * S_) * C_ + h * DH_;

    const int wid  = tid >> 5;
    const int lane = tid & 31;
    const int g    = lane >> 2;
    const int tig  = lane & 3;
    const int warpM = wid & 3;
    const int warpN = wid >> 2;

    const int ld_r = tid >> 2;
    const int ld_c = (tid & 3) * 16;

    // stage Q tile into Ks[0] (pre-rounded; plain copy), extract fragments
    {
        const float* qp = Q + rowbase + (q0 + ld_r) * C_ + ld_c;
#pragma unroll
        for (int j = 0; j < 4; ++j)
            *(uint4*)&Ks[0][ld_r][ld_c + j * 4] = *(const uint4*)(qp + j * 4);
    }
    __syncthreads();

    unsigned bq[4][8][2];
#pragma unroll
    for (int na = 0; na < 4; ++na) {
        const int nc = warpN * 32 + na * 8 + g;
#pragma unroll
        for (int ks = 0; ks < 8; ++ks) {
            bq[na][ks][0] = Ks[0][nc][ks * 8 + tig];
            bq[na][ks][1] = Ks[0][nc][ks * 8 + tig + 4];
        }
    }
    __syncthreads();

    float rmax[4][2];
#pragma unroll
    for (int na = 0; na < 4; ++na) { rmax[na][0] = -1e30f; rmax[na][1] = -1e30f; }

    // prefetch K tile 0 (plain uint4 — K is pre-rounded)
    uint4 kv[4];
    {
        const float* kp = K + rowbase + ld_r * C_ + ld_c;
#pragma unroll
        for (int j = 0; j < 4; ++j) kv[j] = *(const uint4*)(kp + j * 4);
    }

    for (int t = 0; t < S_ / 64; ++t) {
        const int cur = t & 1;
#pragma unroll
        for (int j = 0; j < 4; ++j)
            *(uint4*)&Ks[cur][ld_r][ld_c + j * 4] = kv[j];
        __syncthreads();

        if (t + 1 < S_ / 64) {
            const float* kp = K + rowbase + ((t + 1) * 64 + ld_r) * C_ + ld_c;
#pragma unroll
            for (int j = 0; j < 4; ++j) kv[j] = *(const uint4*)(kp + j * 4);
        }

        float c[4][4];
#pragma unroll
        for (int na = 0; na < 4; ++na)
#pragma unroll
            for (int r = 0; r < 4; ++r) c[na][r] = 0.f;

        const int mr = warpM * 16;
#pragma unroll
        for (int ks = 0; ks < 8; ++ks) {
            const int k0 = ks * 8;
            unsigned a[4];
            a[0] = Ks[cur][mr + g][k0 + tig];
            a[1] = Ks[cur][mr + g + 8][k0 + tig];
            a[2] = Ks[cur][mr + g][k0 + tig + 4];
            a[3] = Ks[cur][mr + g + 8][k0 + tig + 4];
#pragma unroll
            for (int na = 0; na < 4; ++na)
                MMA_TF32(c[na], a, bq[na][ks]);
        }

#pragma unroll
        for (int na = 0; na < 4; ++na) {
            rmax[na][0] = fmaxf(rmax[na][0], fmaxf(c[na][0], c[na][2]));
            rmax[na][1] = fmaxf(rmax[na][1], fmaxf(c[na][1], c[na][3]));
        }
    }

#pragma unroll
    for (int off = 4; off <= 16; off <<= 1)
#pragma unroll
        for (int na = 0; na < 4; ++na) {
            rmax[na][0] = fmaxf(rmax[na][0], __shfl_xor_sync(0xffffffffu, rmax[na][0], off));
            rmax[na][1] = fmaxf(rmax[na][1], __shfl_xor_sync(0xffffffffu, rmax[na][1], off));
        }

    if (g == 0) {
#pragma unroll
        for (int na = 0; na < 4; ++na) {
            buf[warpM][warpN * 32 + na * 8 + tig * 2 + 0] = rmax[na][0];
            buf[warpM][warpN * 32 + na * 8 + tig * 2 + 1] = rmax[na][1];
        }
    }
    __syncthreads();
    if (tid < 64) {
        float m = fmaxf(fmaxf(buf[0][tid], buf[1][tid]),
                        fmaxf(buf[2][tid], buf[3][tid]));
        m1[bh * S_ + q0 + tid] = m * 0.125f;
    }
}

// ============================================================================
// V column sums per (b,h) — V exact fp32
// ============================================================================
__global__ __launch_bounds__(256) void vsum_k(
    const float* __restrict__ V, float* __restrict__ vs)
{
    __shared__ float red[4][64];
    const int bh = blockIdx.x;
    const int b = bh >> 4, h = bh & 15;
    const int tid = threadIdx.x;
    const int d = tid & 63, g = tid >> 6;
    const float* p = V + (b * S_) * C_ + h * DH_ + d;
    float s = 0.f;
    for (int k = g; k < S_; k += 4) s += p[k * C_];
    red[g][d] = s;
    __syncthreads();
    if (tid < 64)
        vs[bh * 64 + tid] = red[0][tid] + red[1][tid] + red[2][tid] + red[3][tid];
}

// ============================================================================
// Tensor-core banded attention (R9-winning structure, static smem;
// Q,K pre-rounded -> plain copies; V rounded in-kernel as before).
// ============================================================================
__global__ __launch_bounds__(256) void band_attn_t(
    const float* __restrict__ Q, const float* __restrict__ K,
    const float* __restrict__ V, const float* __restrict__ m1,
    const float* __restrict__ vs, float* __restrict__ O)
{
    __shared__ unsigned Qs[64][68];
    __shared__ unsigned Ks[32][76];
    __shared__ unsigned Vs[32][76];
    __shared__ unsigned Ws[32][76];
    __shared__ float zred[2][64];

    const int bh = blockIdx.y;
    const int b = bh >> 4, h = bh & 15;
    const int q0 = blockIdx.x * 64;
    const int tid = threadIdx.x;
    const int rowbase = (b * S_) * C_ + h * DH_;

    const int wid  = tid >> 5;
    const int lane = tid & 31;
    const int g    = lane >> 2;
    const int tig  = lane & 3;
    const int wm1 = wid & 1;
    const int wn1 = wid >> 1;
    const int wm2 = wid >> 1;
    const int wn2 = wid & 1;

    {
        const int r  = tid >> 2;
        const int c0 = (tid & 3) * 16;
        const float* qp = Q + rowbase + (q0 + r) * C_ + c0;
#pragma unroll
        for (int j = 0; j < 4; ++j)
            *(uint4*)&Qs[r][c0 + j * 4] = *(const uint4*)(qp + j * 4);
    }
    __syncthreads();

    unsigned bq[2][8][2];
#pragma unroll
    for (int na = 0; na < 2; ++na) {
        const int nc = wn1 * 16 + na * 8 + g;
#pragma unroll
        for (int ks = 0; ks < 8; ++ks) {
            bq[na][ks][0] = Qs[nc][ks * 8 + tig];
            bq[na][ks][1] = Qs[nc][ks * 8 + tig + 4];
        }
    }
    float m1c[2][2];
#pragma unroll
    for (int na = 0; na < 2; ++na) {
        const int qc = q0 + wn1 * 16 + na * 8 + 2 * tig;
        m1c[na][0] = m1[bh * S_ + qc];
        m1c[na][1] = m1[bh * S_ + qc + 1];
    }

    float o[4][4];
#pragma unroll
    for (int na = 0; na < 4; ++na)
#pragma unroll
        for (int r = 0; r < 4; ++r) o[na][r] = 0.f;
    float zp[2][2] = {{0.f, 0.f}, {0.f, 0.f}};

    const int klo  = (q0 >= 128) ? q0 - 128 : 0;
    const int kend = (q0 + 192 < S_) ? q0 + 192 : S_;

    for (int kt = klo; kt < kend; kt += 32) {
        __syncthreads();
        {
            const int r  = tid >> 3;
            const int c0 = (tid & 7) * 8;
            const float* kp = K + rowbase + (kt + r) * C_ + c0;
            const float* vp = V + rowbase + (kt + r) * C_ + c0;
#pragma unroll
            for (int j = 0; j < 2; ++j) {
                // K pre-rounded: plain copy
                *(uint4*)&Ks[r][c0 + j * 4] = *(const uint4*)(kp + j * 4);
                // V exact fp32: round here (same numerics as R9 winner)
                float4 c = *(const float4*)(vp + j * 4);
                uint4 tc;
                tc.x = f2tf(c.x); tc.y = f2tf(c.y); tc.z = f2tf(c.z); tc.w = f2tf(c.w);
                *(uint4*)&Vs[r][c0 + j * 4] = tc;
            }
        }
        __syncthreads();

        float s[2][4];
#pragma unroll
        for (int na = 0; na < 2; ++na)
#pragma unroll
            for (int r = 0; r < 4; ++r) s[na][r] = 0.f;

        const int mr1 = wm1 * 16;
#pragma unroll
        for (int ks = 0; ks < 8; ++ks) {
            const int k0 = ks * 8;
            unsigned a[4];
            a[0] = Ks[mr1 + g][k0 + tig];
            a[1] = Ks[mr1 + g + 8][k0 + tig];
            a[2] = Ks[mr1 + g][k0 + tig + 4];
            a[3] = Ks[mr1 + g + 8][k0 + tig + 4];
            MMA_TF32(s[0], a, bq[0][ks]);
            MMA_TF32(s[1], a, bq[1][ks]);
        }

#pragma unroll
        for (int na = 0; na < 2; ++na) {
            const int colq = wn1 * 16 + na * 8 + 2 * tig;
#pragma unroll
            for (int r2 = 0; r2 < 2; ++r2) {
                const int keyrow = wm1 * 16 + g + r2 * 8;
                const int key = kt + keyrow;
#pragma unroll
                for (int j = 0; j < 2; ++j) {
                    const float sv = s[na][r2 * 2 + j];
                    const int d = key - (q0 + colq + j);
                    float tt = __expf(sv * 0.125f - m1c[na][j]);
                    float w = __expf(tt) - 1.0f;
                    if (d < -128 || d > 127) w = 0.f;
                    const unsigned wt = f2tf(w);
                    zp[na][j] += __uint_as_float(wt);
                    Ws[keyrow][colq + j] = wt;
                }
            }
        }
        __syncthreads();

        const int mr2 = wm2 * 16;
#pragma unroll
        for (int ks = 0; ks < 4; ++ks) {
            const int k0 = ks * 8;
            unsigned a[4];
            a[0] = Ws[k0 + tig][mr2 + g];
            a[1] = Ws[k0 + tig][mr2 + g + 8];
            a[2] = Ws[k0 + tig + 4][mr2 + g];
            a[3] = Ws[k0 + tig + 4][mr2 + g + 8];
#pragma unroll
            for (int na = 0; na < 4; ++na) {
                unsigned bb[2];
                const int nc = wn2 * 32 + na * 8 + g;
                bb[0] = Vs[k0 + tig][nc];
                bb[1] = Vs[k0 + tig + 4][nc];
                MMA_TF32(o[na], a, bb);
            }
        }
    }

#pragma unroll
    for (int off = 4; off <= 16; off <<= 1)
#pragma unroll
        for (int na = 0; na < 2; ++na) {
            zp[na][0] += __shfl_xor_sync(0xffffffffu, zp[na][0], off);
            zp[na][1] += __shfl_xor_sync(0xffffffffu, zp[na][1], off);
        }
    if (g == 0) {
#pragma unroll
        for (int na = 0; na < 2; ++na) {
            zred[wm1][wn1 * 16 + na * 8 + 2 * tig + 0] = zp[na][0];
            zred[wm1][wn1 * 16 + na * 8 + 2 * tig + 1] = zp[na][1];
        }
    }
    __syncthreads();

    const float* vsp = vs + bh * 64;
#pragma unroll
    for (int r2 = 0; r2 < 2; ++r2) {
        const int row = wm2 * 16 + g + r2 * 8;
        const float inv = 1.0f / ((float)S_ + zred[0][row] + zred[1][row]);
        float* op = O + rowbase + (q0 + row) * C_;
#pragma unroll
        for (int na = 0; na < 4; ++na) {
            const int col = wn2 * 32 + na * 8 + 2 * tig;
            float2 ov;
            ov.x = __uint_as_float(f2tf((o[na][r2 * 2 + 0] + vsp[col])     * inv));
            ov.y = __uint_as_float(f2tf((o[na][r2 * 2 + 1] + vsp[col + 1]) * inv));
            *(float2*)(op + col) = ov;
        }
    }
}

// ============================================================================
extern "C" void kernel_launch(void* const* d_in, const int* in_sizes, int n_in,
                              void* d_out, int out_size)
{
    (void)in_sizes; (void)n_in; (void)out_size;
    const float* x  = (const float*)d_in[0];
    const float* Wq = (const float*)d_in[1];
    const float* Wk = (const float*)d_in[2];
    const float* Wv = (const float*)d_in[3];
    const float* Wo = (const float*)d_in[4];
    float* out = (float*)d_out;

    float *Qp, *Kp, *Vp, *Ap, *Xp, *Wtp, *m1p, *vsp;
    cudaGetSymbolAddress((void**)&Qp,  g_Q);
    cudaGetSymbolAddress((void**)&Kp,  g_K);
    cudaGetSymbolAddress((void**)&Vp,  g_V);
    cudaGetSymbolAddress((void**)&Ap,  g_A);
    cudaGetSymbolAddress((void**)&Xp,  g_X);
    cudaGetSymbolAddress((void**)&Wtp, g_Wt);
    cudaGetSymbolAddress((void**)&m1p, g_m1);
    cudaGetSymbolAddress((void**)&vsp, g_vs);

    cudaFuncSetAttribute(tgemm_ca,
                         cudaFuncAttributeMaxDynamicSharedMemorySize,
                         GEMM_SMEM_BYTES);
    cudaFuncSetAttribute(tgemm_ca_qkv,
                         cudaFuncAttributeMaxDynamicSharedMemorySize,
                         GEMM_SMEM_BYTES);

    // one fused rounding launch: x (1M float4) + 4 weights (1M float4)
    round_all<<<(2 * 1024 * 1024) / 256, 256>>>(x, Wq, Wk, Wv, Wo, Xp, Wtp);

    dim3 gq(C_ / 128, M_ / 128, 3);         // (8, 32, 3)
    tgemm_ca_qkv<<<gq, 256, GEMM_SMEM_BYTES>>>(Xp, Wtp, Qp, Kp, Vp);

    score_max_t<<<dim3(S_ / 64, B_ * H_), 256>>>(Qp, Kp, m1p);
    vsum_k<<<B_ * H_, 256>>>(Vp, vsp);
    band_attn_t<<<dim3(S_ / 64, B_ * H_), 256>>>(Qp, Kp, Vp, m1p, vsp, Ap);

    dim3 gg(C_ / 128, M_ / 128);            // (8, 32)
    tgemm_ca<<<gg, 256, GEMM_SMEM_BYTES>>>(Ap, Wtp + 3 * C_ * C_, out, C_, C_);
}